// round 4
// baseline (speedup 1.0000x reference)
#include <cuda_runtime.h>
#include <cstdint>

#define Bz   256
#define Tz   512
#define Ez   200
#define Hz   100
#define NCz  5
#define BT   131072      // B*T

typedef unsigned long long ull;

// ---------------- scratch ----------------
__device__ float g_scale[BT];
__device__ float g_xp[(size_t)BT * 300];   // 157 MB
__device__ float g_state[Bz * Hz];

// ---------------- helpers ----------------
__device__ __forceinline__ float sigf(float x) {
    return 1.0f / (1.0f + __expf(-x));
}
__device__ __forceinline__ float tanh_fast(float x) {
    float t = __expf(-2.0f * fabsf(x));
    float r = (1.0f - t) / (1.0f + t);
    return copysignf(r, x);
}
__device__ __forceinline__ float to_tf32(float x) {
    uint32_t u;
    asm("cvt.rna.tf32.f32 %0, %1;" : "=r"(u) : "f"(x));
    return __uint_as_float(u);
}
__device__ __forceinline__ void fma2(ull& d, ull a, ull b) {
    asm("fma.rn.f32x2 %0, %1, %2, %0;" : "+l"(d) : "l"(a), "l"(b));
}
__device__ __forceinline__ float upksum(ull v) {
    float lo, hi;
    asm("mov.b64 {%0,%1}, %2;" : "=f"(lo), "=f"(hi) : "l"(v));
    return lo + hi;
}

// ---------------- K1: per-row embedding norm scale ----------------
__global__ void __launch_bounds__(256) scale_kernel(const int* __restrict__ txt,
                                                    const float* __restrict__ emb) {
    int warp = (blockIdx.x * 256 + threadIdx.x) >> 5;
    int lane = threadIdx.x & 31;
    if (warp >= BT) return;
    int tok = txt[warp];
    const float* row = emb + (size_t)tok * Ez;
    float ss = 0.f;
    for (int k = lane; k < Ez; k += 32) { float v = row[k]; ss += v * v; }
    #pragma unroll
    for (int o = 16; o > 0; o >>= 1) ss += __shfl_xor_sync(0xffffffffu, ss, o);
    if (lane == 0) {
        float n = sqrtf(ss);
        g_scale[warp] = (n > 1.0f) ? 1.0f / (n + 1e-7f) : 1.0f;
    }
}

// ---------------- K2: tf32 MMA GEMM (xp = norm(emb[txt]) @ W_ih^T + b_ih) ----------------
template <int KDIM, int KCEIL, int KSTR, int TN, int WNc, bool GATHER>
__global__ void __launch_bounds__(256) mma_gemm_kernel(
    const float* __restrict__ Ain,
    const int* __restrict__ txt,
    const float* __restrict__ emb,
    const float* __restrict__ W,
    const float* __restrict__ bias,
    float* __restrict__ C,
    int NV)
{
    extern __shared__ float sm[];
    float* As = sm;
    float* Bs = sm + 64 * KSTR;
    __shared__ int   s_tok[64];
    __shared__ float s_scl[64];

    const int tid   = threadIdx.x;
    const int rbase = blockIdx.x * 64;
    const int nbase = blockIdx.y * TN;

    if (GATHER) {
        if (tid < 64) {
            int r = rbase + tid;
            s_tok[tid] = txt[r];
            s_scl[tid] = g_scale[r];
        }
        __syncthreads();
    }

    const int K4 = KCEIL / 4;
    for (int e = tid; e < 64 * K4; e += 256) {
        int row = e / K4, k4 = e % K4;
        float4 v = make_float4(0.f, 0.f, 0.f, 0.f);
        if (4 * k4 + 3 < KDIM) {
            if (GATHER) {
                const float4* p = (const float4*)(emb + (size_t)s_tok[row] * KDIM) + k4;
                v = *p;
                float s = s_scl[row];
                v.x *= s; v.y *= s; v.z *= s; v.w *= s;
            } else {
                const float4* p = (const float4*)(Ain + (size_t)(rbase + row) * KDIM) + k4;
                v = *p;
            }
        }
        float4 o = make_float4(to_tf32(v.x), to_tf32(v.y), to_tf32(v.z), to_tf32(v.w));
        *(float4*)(As + row * KSTR + 4 * k4) = o;
    }
    for (int e = tid; e < TN * K4; e += 256) {
        int n = e / K4, k4 = e % K4;
        int ng = nbase + n;
        float4 v = make_float4(0.f, 0.f, 0.f, 0.f);
        if (ng < NV && 4 * k4 + 3 < KDIM) {
            const float4* p = (const float4*)(W + (size_t)ng * KDIM) + k4;
            v = *p;
        }
        float4 o = make_float4(to_tf32(v.x), to_tf32(v.y), to_tf32(v.z), to_tf32(v.w));
        *(float4*)(Bs + n * KSTR + 4 * k4) = o;
    }
    __syncthreads();

    const int wid  = tid >> 5;
    const int lane = tid & 31;
    const int g    = lane >> 2;
    const int tg   = lane & 3;
    const int mwarp = wid & 1;
    const int nwarp = wid >> 1;
    const int NF = WNc / 8;

    float c[2][NF][4];
    #pragma unroll
    for (int mt = 0; mt < 2; mt++)
        #pragma unroll
        for (int nf = 0; nf < NF; nf++)
            #pragma unroll
            for (int i = 0; i < 4; i++) c[mt][nf][i] = 0.f;

    const float* Aw = As + (mwarp * 32) * KSTR;
    const float* Bw = Bs + (nwarp * WNc) * KSTR;

    #pragma unroll 1
    for (int k8 = 0; k8 < KCEIL / 8; k8++) {
        int k0 = k8 * 8;
        uint32_t a[2][4], b[NF][2];
        #pragma unroll
        for (int mt = 0; mt < 2; mt++) {
            const float* ap = Aw + (mt * 16 + g) * KSTR + k0 + tg;
            a[mt][0] = __float_as_uint(ap[0]);
            a[mt][1] = __float_as_uint(ap[8 * KSTR]);
            a[mt][2] = __float_as_uint(ap[4]);
            a[mt][3] = __float_as_uint(ap[8 * KSTR + 4]);
        }
        #pragma unroll
        for (int nf = 0; nf < NF; nf++) {
            const float* bp = Bw + (nf * 8 + g) * KSTR + k0 + tg;
            b[nf][0] = __float_as_uint(bp[0]);
            b[nf][1] = __float_as_uint(bp[4]);
        }
        #pragma unroll
        for (int mt = 0; mt < 2; mt++)
            #pragma unroll
            for (int nf = 0; nf < NF; nf++) {
                asm volatile(
                    "mma.sync.aligned.m16n8k8.row.col.f32.tf32.tf32.f32 "
                    "{%0,%1,%2,%3}, {%4,%5,%6,%7}, {%8,%9}, {%0,%1,%2,%3};"
                    : "+f"(c[mt][nf][0]), "+f"(c[mt][nf][1]),
                      "+f"(c[mt][nf][2]), "+f"(c[mt][nf][3])
                    : "r"(a[mt][0]), "r"(a[mt][1]), "r"(a[mt][2]), "r"(a[mt][3]),
                      "r"(b[nf][0]), "r"(b[nf][1]));
            }
    }

    #pragma unroll
    for (int mt = 0; mt < 2; mt++) {
        int row = rbase + mwarp * 32 + mt * 16 + g;
        #pragma unroll
        for (int nf = 0; nf < NF; nf++) {
            int col = nbase + nwarp * WNc + nf * 8 + 2 * tg;
            if (col < NV) {
                float b0 = bias[col], b1 = bias[col + 1];
                float2 v0 = make_float2(c[mt][nf][0] + b0, c[mt][nf][1] + b1);
                float2 v1 = make_float2(c[mt][nf][2] + b0, c[mt][nf][3] + b1);
                *(float2*)(C + (size_t)row * NV + col) = v0;
                *(float2*)(C + (size_t)(row + 8) * NV + col) = v1;
            }
        }
    }
}

// ============================================================================
// Fused scan: GRU + z/li reductions + ti GEMV + second recurrence.
// 128 blocks (2 batch elems), 544 threads:
//   tid   0-299 : GRU rows (W_hh row in w[0..49] regs); tid<100 also update h
//   tid 300-399 : rec rows j=tid-300, k 0..49  (W_ti half in w[0..24], W_ts in w[25..49])
//                 lo half keeps partials in regs and does the state update in phase 2
//   tid 400-499 : rec rows j=tid-400, k 50..99 -> publish partials to partHi
//   tid 512-543 : warp 16 = x prefetch + 8 length-100 reductions (z, li, pg)
// Rec runs one superstep behind the GRU. Loop s = 0..Tz inclusive.
// ============================================================================
__global__ void __launch_bounds__(544, 1) fused_scan_kernel(
    const float* __restrict__ Whh, const float* __restrict__ bhh,
    const float* __restrict__ Wts, const float* __restrict__ bts,
    const float* __restrict__ Wti, const float* __restrict__ bti,
    const float* __restrict__ Wlgr, const float* __restrict__ blgr,
    const int* __restrict__ lens)
{
    __shared__ __align__(16) float hb[2][2][104];    // h double buffer [parity][batch][k]
    __shared__ __align__(16) float st_s[2][104];     // rec state [batch][k]
    __shared__ float hpre[2][304];                   // GRU pre-activations [batch][row]
    __shared__ float xbuf[2][2][304];                // x double buffer [parity][batch][row]
    __shared__ float partHi[4][100];                 // hi-half partials: ti0,ti1,m0,m1
    __shared__ float wlgr_s[100], wl_s[100];
    __shared__ float red[4];                         // z0,z1,gate0,gate1

    const int tid = threadIdx.x;
    const int b0 = blockIdx.x * 2, b1 = b0 + 1;
    const float* xp0 = g_xp + (size_t)b0 * Tz * 300;
    const float* xp1 = g_xp + (size_t)b1 * Tz * 300;

    const bool isA   = (tid < 300);
    const bool isB   = (tid >= 300 && tid < 500);
    const bool isLo  = (tid >= 300 && tid < 400);
    const bool isRed = (tid >= 512);
    const int  lane  = tid & 31;

    // ---- init shared ----
    if (tid < 104) {
        hb[0][0][tid] = 0.f; hb[0][1][tid] = 0.f;
        hb[1][0][tid] = 0.f; hb[1][1][tid] = 0.f;
        st_s[0][tid] = 0.f;  st_s[1][tid] = 0.f;
    }
    if (tid < 100) {
        wlgr_s[tid] = Wlgr[tid];
        wl_s[tid]   = Wlgr[100 + tid];
    }

    // ---- role-shared weight registers ----
    ull w[50];                      // A: W_hh row. B: [0..24]=W_ti half, [25..49]=W_ts half.
    float bias_a = 0.f, bti_r = 0.f, bts_r = 0.f;
    int   jrow = 0, koff = 0;
    int   lenv = 0; float blg = 0.f;

    if (isA) {
        const ull* wr = (const ull*)(Whh + tid * 100);
        #pragma unroll
        for (int q = 0; q < 50; q++) w[q] = wr[q];
        bias_a = bhh[tid];
    } else if (isB) {
        jrow = isLo ? (tid - 300) : (tid - 400);
        koff = isLo ? 0 : 50;
        const ull* tp = (const ull*)(Wti + jrow * 100 + koff);
        const ull* sp = (const ull*)(Wts + jrow * 100 + koff);
        #pragma unroll
        for (int q = 0; q < 25; q++) { w[q] = tp[q]; w[25 + q] = sp[q]; }
        if (isLo) { bti_r = bti[jrow]; bts_r = bts[jrow]; }
    } else if (isRed) {
        if (lane < 2) lenv = lens[b0 + lane];
        blg = blgr[0];
        for (int i = lane; i < 300; i += 32) {     // prologue: x_0 -> xbuf[0]
            xbuf[0][0][i] = xp0[i];
            xbuf[0][1][i] = xp1[i];
        }
    }
    __syncthreads();

    for (int s = 0; s <= Tz; s++) {
        const int pp = (s & 1) ^ 1;                // parity holding h_{s-1}
        float lo_ti0 = 0.f, lo_ti1 = 0.f, lo_m0 = 0.f, lo_m1 = 0.f;  // lo-half partials

        // ================= phase 1 =================
        if (isA) {
            if (s < Tz) {
                ull a0 = 0ull, a1 = 0ull;
                const ulonglong2* h0 = (const ulonglong2*)&hb[pp][0][0];
                const ulonglong2* h1 = (const ulonglong2*)&hb[pp][1][0];
                #pragma unroll
                for (int v = 0; v < 25; v++) {
                    ulonglong2 hv = h0[v];
                    fma2(a0, w[2 * v],     hv.x);
                    fma2(a0, w[2 * v + 1], hv.y);
                }
                #pragma unroll
                for (int v = 0; v < 25; v++) {
                    ulonglong2 hv = h1[v];
                    fma2(a1, w[2 * v],     hv.x);
                    fma2(a1, w[2 * v + 1], hv.y);
                }
                hpre[0][tid] = bias_a + upksum(a0);
                hpre[1][tid] = bias_a + upksum(a1);
            }
        } else if (isB) {
            if (s >= 1) {
                ull t0 = 0ull, t1 = 0ull, m0 = 0ull, m1 = 0ull;
                const ull* h0 = (const ull*)&hb[pp][0][koff];
                const ull* h1 = (const ull*)&hb[pp][1][koff];
                const ull* s0 = (const ull*)&st_s[0][koff];
                const ull* s1 = (const ull*)&st_s[1][koff];
                #pragma unroll
                for (int q = 0; q < 25; q++) {
                    fma2(t0, w[q],      h0[q]);
                    fma2(t1, w[q],      h1[q]);
                    fma2(m0, w[25 + q], s0[q]);
                    fma2(m1, w[25 + q], s1[q]);
                }
                if (isLo) {
                    lo_ti0 = upksum(t0); lo_ti1 = upksum(t1);
                    lo_m0  = upksum(m0); lo_m1  = upksum(m1);
                } else {
                    partHi[0][jrow] = upksum(t0);
                    partHi[1][jrow] = upksum(t1);
                    partHi[2][jrow] = upksum(m0);
                    partHi[3][jrow] = upksum(m1);
                }
            }
        } else if (isRed) {
            if (s + 1 < Tz) {                      // prefetch x_{s+1}
                const float* px0 = xp0 + (size_t)(s + 1) * 300;
                const float* px1 = xp1 + (size_t)(s + 1) * 300;
                float* xb0 = xbuf[(s + 1) & 1][0];
                float* xb1 = xbuf[(s + 1) & 1][1];
                for (int i = lane; i < 300; i += 32) {
                    xb0[i] = px0[i];
                    xb1[i] = px1[i];
                }
            }
            if (s >= 1) {                          // z_t, li_t, pg over h_{s-1}, st
                float s1_0 = 0.f, s2_0 = 0.f, s3_0 = 0.f;
                float s1_1 = 0.f, s2_1 = 0.f, s3_1 = 0.f;
                float pg0 = 0.f, pg1 = 0.f;
                for (int k = lane; k < 100; k += 32) {
                    float h0 = hb[pp][0][k], h1 = hb[pp][1][k];
                    float wg = wlgr_s[k], wl = wl_s[k];
                    s1_0 += h0; s2_0 += h0 * h0; s3_0 += h0 * wg;
                    s1_1 += h1; s2_1 += h1 * h1; s3_1 += h1 * wg;
                    pg0 += wl * st_s[0][k];
                    pg1 += wl * st_s[1][k];
                }
                #pragma unroll
                for (int o = 16; o > 0; o >>= 1) {
                    s1_0 += __shfl_xor_sync(0xffffffffu, s1_0, o);
                    s2_0 += __shfl_xor_sync(0xffffffffu, s2_0, o);
                    s3_0 += __shfl_xor_sync(0xffffffffu, s3_0, o);
                    s1_1 += __shfl_xor_sync(0xffffffffu, s1_1, o);
                    s2_1 += __shfl_xor_sync(0xffffffffu, s2_1, o);
                    s3_1 += __shfl_xor_sync(0xffffffffu, s3_1, o);
                    pg0  += __shfl_xor_sync(0xffffffffu, pg0, o);
                    pg1  += __shfl_xor_sync(0xffffffffu, pg1, o);
                }
                if (lane < 2) {
                    int t = s - 1;
                    float s1 = lane ? s1_1 : s1_0;
                    float s2 = lane ? s2_1 : s2_0;
                    float s3 = lane ? s3_1 : s3_0;
                    float pg = lane ? pg1  : pg0;
                    float att = 0.001f * s1 / fmaxf(sqrtf(s2), 1e-12f);
                    float zv = (t < lenv && att > 0.f) ? att : 0.f;
                    red[lane]     = zv;
                    red[2 + lane] = sigf(s3 + pg + blg);
                }
            }
        }
        __syncthreads();

        // ================= phase 2 =================
        if (tid < 100 && s < Tz) {
            const int pc = s & 1;
            const float* xb0 = xbuf[pc][0];
            const float* xb1 = xbuf[pc][1];
            float hr0 = hpre[0][tid], hz0 = hpre[0][100 + tid], hn0 = hpre[0][200 + tid];
            float hr1 = hpre[1][tid], hz1 = hpre[1][100 + tid], hn1 = hpre[1][200 + tid];
            float ho0 = hb[pp][0][tid], ho1 = hb[pp][1][tid];
            float r0 = sigf(xb0[tid] + hr0),        r1 = sigf(xb1[tid] + hr1);
            float z0 = sigf(xb0[100 + tid] + hz0),  z1 = sigf(xb1[100 + tid] + hz1);
            float n0 = tanh_fast(xb0[200 + tid] + r0 * hn0);
            float n1 = tanh_fast(xb1[200 + tid] + r1 * hn1);
            hb[pc][0][tid] = (1.f - z0) * n0 + z0 * ho0;
            hb[pc][1][tid] = (1.f - z1) * n1 + z1 * ho1;
        } else if (isLo && s >= 1) {
            int j = jrow;
            float gz0 = red[0], gz1 = red[1];
            float gg0 = red[2], gg1 = red[3];
            float ti0 = lo_ti0 + partHi[0][j] + bti_r;
            float ti1 = lo_ti1 + partHi[1][j] + bti_r;
            float mm0 = lo_m0  + partHi[2][j];
            float mm1 = lo_m1  + partHi[3][j];
            float so0 = st_s[0][j], so1 = st_s[1][j];
            float ns0 = tanh_fast(ti0 + gg0 * mm0 + bts_r);
            float ns1 = tanh_fast(ti1 + gg1 * mm1 + bts_r);
            st_s[0][j] = (1.f - gz0) * so0 + gz0 * ns0;
            st_s[1][j] = (1.f - gz1) * so1 + gz1 * ns1;
        }
        __syncthreads();
    }

    if (tid < 100) {
        g_state[b0 * Hz + tid] = st_s[0][tid];
        g_state[b1 * Hz + tid] = st_s[1][tid];
    }
}

// ---------------- K7: output projection ----------------
__global__ void __launch_bounds__(256) out_kernel(const float* __restrict__ Wout,
                                                  const float* __restrict__ bout,
                                                  float* __restrict__ out) {
    int idx = blockIdx.x * 256 + threadIdx.x;
    if (idx >= Bz * NCz) return;
    int b = idx / NCz, c = idx % NCz;
    float acc = bout[c];
    const float* s = g_state + b * Hz;
    const float* wr = Wout + c * Hz;
    #pragma unroll
    for (int k = 0; k < Hz; k++) acc += s[k] * wr[k];
    out[idx] = acc;
}

// ---------------- launch ----------------
extern "C" void kernel_launch(void* const* d_in, const int* in_sizes, int n_in,
                              void* d_out, int out_size) {
    const int*   txt   = (const int*)d_in[0];
    const int*   lens  = (const int*)d_in[1];
    const float* emb   = (const float*)d_in[2];
    const float* W_ih  = (const float*)d_in[3];
    const float* W_hh  = (const float*)d_in[4];
    const float* b_ih  = (const float*)d_in[5];
    const float* b_hh  = (const float*)d_in[6];
    const float* W_lgr = (const float*)d_in[7];
    const float* b_lgr = (const float*)d_in[8];
    const float* W_ts  = (const float*)d_in[9];
    const float* b_ts  = (const float*)d_in[10];
    const float* W_ti  = (const float*)d_in[11];
    const float* b_ti  = (const float*)d_in[12];
    const float* W_out = (const float*)d_in[13];
    const float* b_out = (const float*)d_in[14];
    float* out = (float*)d_out;

    float* xp = nullptr; cudaGetSymbolAddress((void**)&xp, g_xp);

    scale_kernel<<<BT / 8, 256>>>(txt, emb);

    {
        constexpr int SMEM = (64 + 160) * 204 * 4;
        cudaFuncSetAttribute((const void*)mma_gemm_kernel<200, 200, 204, 160, 40, true>,
                             cudaFuncAttributeMaxDynamicSharedMemorySize, SMEM);
        dim3 grid(BT / 64, 2);
        mma_gemm_kernel<200, 200, 204, 160, 40, true><<<grid, 256, SMEM>>>(
            nullptr, txt, emb, W_ih, b_ih, xp, 300);
    }

    fused_scan_kernel<<<Bz / 2, 544>>>(W_hh, b_hh, W_ts, b_ts, W_ti, b_ti,
                                       W_lgr, b_lgr, lens);

    out_kernel<<<(Bz * NCz + 255) / 256, 256>>>(W_out, b_out, out);
}

// round 5
// speedup vs baseline: 1.2600x; 1.2600x over previous
#include <cuda_runtime.h>
#include <cstdint>

#define Bz   256
#define Tz   512
#define Ez   200
#define Hz   100
#define NCz  5
#define BT   131072      // B*T

typedef unsigned long long ull;

// ---------------- scratch ----------------
__device__ float g_scale[BT];
__device__ float g_xp[(size_t)BT * 300];   // 157 MB
__device__ float g_state[Bz * Hz];

// ---------------- helpers ----------------
__device__ __forceinline__ float sigf(float x) {
    return 1.0f / (1.0f + __expf(-x));
}
__device__ __forceinline__ float tanh_fast(float x) {
    float t = __expf(-2.0f * fabsf(x));
    float r = (1.0f - t) / (1.0f + t);
    return copysignf(r, x);
}
__device__ __forceinline__ float to_tf32(float x) {
    uint32_t u;
    asm("cvt.rna.tf32.f32 %0, %1;" : "=r"(u) : "f"(x));
    return __uint_as_float(u);
}
__device__ __forceinline__ void fma2(ull& d, ull a, ull b) {
    asm("fma.rn.f32x2 %0, %1, %2, %0;" : "+l"(d) : "l"(a), "l"(b));
}
__device__ __forceinline__ float upksum(ull v) {
    float lo, hi;
    asm("mov.b64 {%0,%1}, %2;" : "=f"(lo), "=f"(hi) : "l"(v));
    return lo + hi;
}

// ---------------- K1: per-row embedding norm scale ----------------
__global__ void __launch_bounds__(256) scale_kernel(const int* __restrict__ txt,
                                                    const float* __restrict__ emb) {
    int warp = (blockIdx.x * 256 + threadIdx.x) >> 5;
    int lane = threadIdx.x & 31;
    if (warp >= BT) return;
    int tok = txt[warp];
    const float* row = emb + (size_t)tok * Ez;
    float ss = 0.f;
    for (int k = lane; k < Ez; k += 32) { float v = row[k]; ss += v * v; }
    #pragma unroll
    for (int o = 16; o > 0; o >>= 1) ss += __shfl_xor_sync(0xffffffffu, ss, o);
    if (lane == 0) {
        float n = sqrtf(ss);
        g_scale[warp] = (n > 1.0f) ? 1.0f / (n + 1e-7f) : 1.0f;
    }
}

// ---------------- K2: tf32 MMA GEMM (xp = norm(emb[txt]) @ W_ih^T + b_ih) ----------------
template <int KDIM, int KCEIL, int KSTR, int TN, int WNc, bool GATHER>
__global__ void __launch_bounds__(256) mma_gemm_kernel(
    const float* __restrict__ Ain,
    const int* __restrict__ txt,
    const float* __restrict__ emb,
    const float* __restrict__ W,
    const float* __restrict__ bias,
    float* __restrict__ C,
    int NV)
{
    extern __shared__ float sm[];
    float* As = sm;
    float* Bs = sm + 64 * KSTR;
    __shared__ int   s_tok[64];
    __shared__ float s_scl[64];

    const int tid   = threadIdx.x;
    const int rbase = blockIdx.x * 64;
    const int nbase = blockIdx.y * TN;

    if (GATHER) {
        if (tid < 64) {
            int r = rbase + tid;
            s_tok[tid] = txt[r];
            s_scl[tid] = g_scale[r];
        }
        __syncthreads();
    }

    const int K4 = KCEIL / 4;
    for (int e = tid; e < 64 * K4; e += 256) {
        int row = e / K4, k4 = e % K4;
        float4 v = make_float4(0.f, 0.f, 0.f, 0.f);
        if (4 * k4 + 3 < KDIM) {
            if (GATHER) {
                const float4* p = (const float4*)(emb + (size_t)s_tok[row] * KDIM) + k4;
                v = *p;
                float s = s_scl[row];
                v.x *= s; v.y *= s; v.z *= s; v.w *= s;
            } else {
                const float4* p = (const float4*)(Ain + (size_t)(rbase + row) * KDIM) + k4;
                v = *p;
            }
        }
        float4 o = make_float4(to_tf32(v.x), to_tf32(v.y), to_tf32(v.z), to_tf32(v.w));
        *(float4*)(As + row * KSTR + 4 * k4) = o;
    }
    for (int e = tid; e < TN * K4; e += 256) {
        int n = e / K4, k4 = e % K4;
        int ng = nbase + n;
        float4 v = make_float4(0.f, 0.f, 0.f, 0.f);
        if (ng < NV && 4 * k4 + 3 < KDIM) {
            const float4* p = (const float4*)(W + (size_t)ng * KDIM) + k4;
            v = *p;
        }
        float4 o = make_float4(to_tf32(v.x), to_tf32(v.y), to_tf32(v.z), to_tf32(v.w));
        *(float4*)(Bs + n * KSTR + 4 * k4) = o;
    }
    __syncthreads();

    const int wid  = tid >> 5;
    const int lane = tid & 31;
    const int g    = lane >> 2;
    const int tg   = lane & 3;
    const int mwarp = wid & 1;
    const int nwarp = wid >> 1;
    const int NF = WNc / 8;

    float c[2][NF][4];
    #pragma unroll
    for (int mt = 0; mt < 2; mt++)
        #pragma unroll
        for (int nf = 0; nf < NF; nf++)
            #pragma unroll
            for (int i = 0; i < 4; i++) c[mt][nf][i] = 0.f;

    const float* Aw = As + (mwarp * 32) * KSTR;
    const float* Bw = Bs + (nwarp * WNc) * KSTR;

    #pragma unroll 1
    for (int k8 = 0; k8 < KCEIL / 8; k8++) {
        int k0 = k8 * 8;
        uint32_t a[2][4], b[NF][2];
        #pragma unroll
        for (int mt = 0; mt < 2; mt++) {
            const float* ap = Aw + (mt * 16 + g) * KSTR + k0 + tg;
            a[mt][0] = __float_as_uint(ap[0]);
            a[mt][1] = __float_as_uint(ap[8 * KSTR]);
            a[mt][2] = __float_as_uint(ap[4]);
            a[mt][3] = __float_as_uint(ap[8 * KSTR + 4]);
        }
        #pragma unroll
        for (int nf = 0; nf < NF; nf++) {
            const float* bp = Bw + (nf * 8 + g) * KSTR + k0 + tg;
            b[nf][0] = __float_as_uint(bp[0]);
            b[nf][1] = __float_as_uint(bp[4]);
        }
        #pragma unroll
        for (int mt = 0; mt < 2; mt++)
            #pragma unroll
            for (int nf = 0; nf < NF; nf++) {
                asm volatile(
                    "mma.sync.aligned.m16n8k8.row.col.f32.tf32.tf32.f32 "
                    "{%0,%1,%2,%3}, {%4,%5,%6,%7}, {%8,%9}, {%0,%1,%2,%3};"
                    : "+f"(c[mt][nf][0]), "+f"(c[mt][nf][1]),
                      "+f"(c[mt][nf][2]), "+f"(c[mt][nf][3])
                    : "r"(a[mt][0]), "r"(a[mt][1]), "r"(a[mt][2]), "r"(a[mt][3]),
                      "r"(b[nf][0]), "r"(b[nf][1]));
            }
    }

    #pragma unroll
    for (int mt = 0; mt < 2; mt++) {
        int row = rbase + mwarp * 32 + mt * 16 + g;
        #pragma unroll
        for (int nf = 0; nf < NF; nf++) {
            int col = nbase + nwarp * WNc + nf * 8 + 2 * tg;
            if (col < NV) {
                float b0 = bias[col], b1 = bias[col + 1];
                float2 v0 = make_float2(c[mt][nf][0] + b0, c[mt][nf][1] + b1);
                float2 v1 = make_float2(c[mt][nf][2] + b0, c[mt][nf][3] + b1);
                *(float2*)(C + (size_t)row * NV + col) = v0;
                *(float2*)(C + (size_t)(row + 8) * NV + col) = v1;
            }
        }
    }
}

// ============================================================================
// Fused scan. 128 blocks (2 batch elems), 480 threads (15 warps), <=136 regs:
//   tid   0-299 (warps 0-9) : A = GRU rows, W_hh row in w[50] ull regs
//   tid 320-419 (warps 10-13): B = rec row j=tid-320 (full K):
//       phase 1: ti = W_ti@h (W_ti row reuses w[] regs), m = W_ts@st (W_ts in smem)
//                + LDG x_{s+1} into xnext regs
//       phase 2: GRU h-update for row j (uses xcur regs) + rec state update
//   tid 448-479 (warp 14)   : reductions (z, li, pg) -> red[4]
// B runs one superstep behind the GRU. Loop s = 0..Tz inclusive.
// W_ts in dynamic smem [100][108] (quad-bank conflict-free for LDS.128).
// ============================================================================
__global__ void __launch_bounds__(480, 1) fused_scan_kernel(
    const float* __restrict__ Whh, const float* __restrict__ bhh,
    const float* __restrict__ Wts, const float* __restrict__ bts,
    const float* __restrict__ Wti, const float* __restrict__ bti,
    const float* __restrict__ Wlgr, const float* __restrict__ blgr,
    const int* __restrict__ lens)
{
    extern __shared__ __align__(16) float wts_sh[];  // [100][108] = 43200 B
    __shared__ __align__(16) float hb[2][2][104];    // h double buffer [parity][batch][k]
    __shared__ __align__(16) float st_s[2][104];     // rec state [batch][k]
    __shared__ float hpre[2][304];                   // GRU pre-activations [batch][row]
    __shared__ float wlgr_s[100], wl_s[100];
    __shared__ float red[4];                         // z0,z1,gate0,gate1

    const int tid = threadIdx.x;
    const int b0 = blockIdx.x * 2, b1 = b0 + 1;
    const float* xp0 = g_xp + (size_t)b0 * Tz * 300;
    const float* xp1 = g_xp + (size_t)b1 * Tz * 300;

    const bool isA   = (tid < 300);
    const bool isB   = (tid >= 320 && tid < 420);
    const bool isRed = (tid >= 448);
    const int  lane  = tid & 31;
    const int  jrow  = tid - 320;                    // B row (valid when isB)

    // ---- load W_ts into padded shared ----
    for (int i = tid; i < 100 * 100; i += 480)
        wts_sh[(i / 100) * 108 + (i % 100)] = Wts[i];

    // ---- init shared ----
    if (tid < 104) {
        hb[0][0][tid] = 0.f; hb[0][1][tid] = 0.f;
        hb[1][0][tid] = 0.f; hb[1][1][tid] = 0.f;
        st_s[0][tid] = 0.f;  st_s[1][tid] = 0.f;
    }
    if (tid < 100) {
        wlgr_s[tid] = Wlgr[tid];
        wl_s[tid]   = Wlgr[100 + tid];
    }

    // ---- role registers ----
    ull w[50];                 // A: W_hh row. B: W_ti row.
    float bias_a = 0.f, bti_r = 0.f, bts_r = 0.f;
    int   lenv = 0; float blg = 0.f;
    // B x-pipeline registers (x for current step / next step)
    float xr0c = 0.f, xz0c = 0.f, xn0c = 0.f, xr1c = 0.f, xz1c = 0.f, xn1c = 0.f;
    float xr0n = 0.f, xz0n = 0.f, xn0n = 0.f, xr1n = 0.f, xz1n = 0.f, xn1n = 0.f;

    if (isA) {
        const ull* wr = (const ull*)(Whh + tid * 100);
        #pragma unroll
        for (int q = 0; q < 50; q++) w[q] = wr[q];
        bias_a = bhh[tid];
    } else if (isB) {
        const ull* wr = (const ull*)(Wti + jrow * 100);
        #pragma unroll
        for (int q = 0; q < 50; q++) w[q] = wr[q];
        bti_r = bti[jrow];
        bts_r = bts[jrow];
        // prologue: x_0
        xr0c = xp0[jrow];       xr1c = xp1[jrow];
        xz0c = xp0[100 + jrow]; xz1c = xp1[100 + jrow];
        xn0c = xp0[200 + jrow]; xn1c = xp1[200 + jrow];
    } else if (isRed) {
        if (lane < 2) lenv = lens[b0 + lane];
        blg = blgr[0];
    }
    __syncthreads();

    for (int s = 0; s <= Tz; s++) {
        const int pp = (s & 1) ^ 1;                 // parity holding h_{s-1}
        float ti0 = 0.f, ti1 = 0.f, mm0 = 0.f, mm1 = 0.f;   // B phase-1 results

        // ================= phase 1 =================
        if (isA) {
            if (s < Tz) {
                ull a0 = 0ull, a1 = 0ull;
                const ulonglong2* h0 = (const ulonglong2*)&hb[pp][0][0];
                const ulonglong2* h1 = (const ulonglong2*)&hb[pp][1][0];
                #pragma unroll
                for (int v = 0; v < 25; v++) {
                    ulonglong2 hv = h0[v];
                    fma2(a0, w[2 * v],     hv.x);
                    fma2(a0, w[2 * v + 1], hv.y);
                }
                #pragma unroll
                for (int v = 0; v < 25; v++) {
                    ulonglong2 hv = h1[v];
                    fma2(a1, w[2 * v],     hv.x);
                    fma2(a1, w[2 * v + 1], hv.y);
                }
                hpre[0][tid] = bias_a + upksum(a0);
                hpre[1][tid] = bias_a + upksum(a1);
            }
        } else if (isB) {
            // issue x prefetch for step s+1 first (latency hidden by matvec)
            if (s + 1 < Tz) {
                const float* p0 = xp0 + (size_t)(s + 1) * 300;
                const float* p1 = xp1 + (size_t)(s + 1) * 300;
                xr0n = p0[jrow];       xr1n = p1[jrow];
                xz0n = p0[100 + jrow]; xz1n = p1[100 + jrow];
                xn0n = p0[200 + jrow]; xn1n = p1[200 + jrow];
            }
            if (s >= 1) {
                // ti = W_ti @ h_{s-1}   (w regs, fma2)
                ull t0 = 0ull, t1 = 0ull;
                const ulonglong2* h0 = (const ulonglong2*)&hb[pp][0][0];
                const ulonglong2* h1 = (const ulonglong2*)&hb[pp][1][0];
                #pragma unroll
                for (int v = 0; v < 25; v++) {
                    ulonglong2 hv = h0[v];
                    fma2(t0, w[2 * v],     hv.x);
                    fma2(t0, w[2 * v + 1], hv.y);
                }
                #pragma unroll
                for (int v = 0; v < 25; v++) {
                    ulonglong2 hv = h1[v];
                    fma2(t1, w[2 * v],     hv.x);
                    fma2(t1, w[2 * v + 1], hv.y);
                }
                ti0 = upksum(t0) + bti_r;
                ti1 = upksum(t1) + bti_r;
                // m = W_ts @ st_{s-2}   (W_ts from shared, float4)
                const float4* wsr = (const float4*)&wts_sh[jrow * 108];
                const float4* s0p = (const float4*)&st_s[0][0];
                const float4* s1p = (const float4*)&st_s[1][0];
                #pragma unroll
                for (int q = 0; q < 25; q++) {
                    float4 wv = wsr[q];
                    float4 a4 = s0p[q];
                    float4 b4 = s1p[q];
                    mm0 += wv.x * a4.x + wv.y * a4.y + wv.z * a4.z + wv.w * a4.w;
                    mm1 += wv.x * b4.x + wv.y * b4.y + wv.z * b4.z + wv.w * b4.w;
                }
            }
        } else if (isRed) {
            if (s >= 1) {
                float s1_0 = 0.f, s2_0 = 0.f, s3_0 = 0.f;
                float s1_1 = 0.f, s2_1 = 0.f, s3_1 = 0.f;
                float pg0 = 0.f, pg1 = 0.f;
                for (int k = lane; k < 100; k += 32) {
                    float h0 = hb[pp][0][k], h1 = hb[pp][1][k];
                    float wg = wlgr_s[k], wl = wl_s[k];
                    s1_0 += h0; s2_0 += h0 * h0; s3_0 += h0 * wg;
                    s1_1 += h1; s2_1 += h1 * h1; s3_1 += h1 * wg;
                    pg0 += wl * st_s[0][k];
                    pg1 += wl * st_s[1][k];
                }
                #pragma unroll
                for (int o = 16; o > 0; o >>= 1) {
                    s1_0 += __shfl_xor_sync(0xffffffffu, s1_0, o);
                    s2_0 += __shfl_xor_sync(0xffffffffu, s2_0, o);
                    s3_0 += __shfl_xor_sync(0xffffffffu, s3_0, o);
                    s1_1 += __shfl_xor_sync(0xffffffffu, s1_1, o);
                    s2_1 += __shfl_xor_sync(0xffffffffu, s2_1, o);
                    s3_1 += __shfl_xor_sync(0xffffffffu, s3_1, o);
                    pg0  += __shfl_xor_sync(0xffffffffu, pg0, o);
                    pg1  += __shfl_xor_sync(0xffffffffu, pg1, o);
                }
                if (lane < 2) {
                    int t = s - 1;
                    float s1 = lane ? s1_1 : s1_0;
                    float s2 = lane ? s2_1 : s2_0;
                    float s3 = lane ? s3_1 : s3_0;
                    float pg = lane ? pg1  : pg0;
                    float att = 0.001f * s1 / fmaxf(sqrtf(s2), 1e-12f);
                    float zv = (t < lenv && att > 0.f) ? att : 0.f;
                    red[lane]     = zv;
                    red[2 + lane] = sigf(s3 + pg + blg);
                }
            }
        }
        __syncthreads();

        // ================= phase 2 (B threads only) =================
        if (isB) {
            if (s < Tz) {
                // GRU h-update for row jrow
                float hr0 = hpre[0][jrow], hz0 = hpre[0][100 + jrow], hn0 = hpre[0][200 + jrow];
                float hr1 = hpre[1][jrow], hz1 = hpre[1][100 + jrow], hn1 = hpre[1][200 + jrow];
                float ho0 = hb[pp][0][jrow], ho1 = hb[pp][1][jrow];
                float r0 = sigf(xr0c + hr0), r1 = sigf(xr1c + hr1);
                float z0 = sigf(xz0c + hz0), z1 = sigf(xz1c + hz1);
                float n0 = tanh_fast(xn0c + r0 * hn0);
                float n1 = tanh_fast(xn1c + r1 * hn1);
                const int pc = s & 1;
                hb[pc][0][jrow] = (1.f - z0) * n0 + z0 * ho0;
                hb[pc][1][jrow] = (1.f - z1) * n1 + z1 * ho1;
                // rotate x pipeline
                xr0c = xr0n; xz0c = xz0n; xn0c = xn0n;
                xr1c = xr1n; xz1c = xz1n; xn1c = xn1n;
            }
            if (s >= 1) {
                // rec state update for row jrow (step t = s-1)
                float gz0 = red[0], gz1 = red[1];
                float gg0 = red[2], gg1 = red[3];
                float so0 = st_s[0][jrow], so1 = st_s[1][jrow];
                float ns0 = tanh_fast(ti0 + gg0 * mm0 + bts_r);
                float ns1 = tanh_fast(ti1 + gg1 * mm1 + bts_r);
                st_s[0][jrow] = (1.f - gz0) * so0 + gz0 * ns0;
                st_s[1][jrow] = (1.f - gz1) * so1 + gz1 * ns1;
            }
        }
        __syncthreads();
    }

    if (isB) {
        g_state[b0 * Hz + jrow] = st_s[0][jrow];
        g_state[b1 * Hz + jrow] = st_s[1][jrow];
    }
}

// ---------------- K7: output projection ----------------
__global__ void __launch_bounds__(256) out_kernel(const float* __restrict__ Wout,
                                                  const float* __restrict__ bout,
                                                  float* __restrict__ out) {
    int idx = blockIdx.x * 256 + threadIdx.x;
    if (idx >= Bz * NCz) return;
    int b = idx / NCz, c = idx % NCz;
    float acc = bout[c];
    const float* s = g_state + b * Hz;
    const float* wr = Wout + c * Hz;
    #pragma unroll
    for (int k = 0; k < Hz; k++) acc += s[k] * wr[k];
    out[idx] = acc;
}

// ---------------- launch ----------------
extern "C" void kernel_launch(void* const* d_in, const int* in_sizes, int n_in,
                              void* d_out, int out_size) {
    const int*   txt   = (const int*)d_in[0];
    const int*   lens  = (const int*)d_in[1];
    const float* emb   = (const float*)d_in[2];
    const float* W_ih  = (const float*)d_in[3];
    const float* W_hh  = (const float*)d_in[4];
    const float* b_ih  = (const float*)d_in[5];
    const float* b_hh  = (const float*)d_in[6];
    const float* W_lgr = (const float*)d_in[7];
    const float* b_lgr = (const float*)d_in[8];
    const float* W_ts  = (const float*)d_in[9];
    const float* b_ts  = (const float*)d_in[10];
    const float* W_ti  = (const float*)d_in[11];
    const float* b_ti  = (const float*)d_in[12];
    const float* W_out = (const float*)d_in[13];
    const float* b_out = (const float*)d_in[14];
    float* out = (float*)d_out;

    float* xp = nullptr; cudaGetSymbolAddress((void**)&xp, g_xp);

    scale_kernel<<<BT / 8, 256>>>(txt, emb);

    {
        constexpr int SMEM = (64 + 160) * 204 * 4;
        cudaFuncSetAttribute((const void*)mma_gemm_kernel<200, 200, 204, 160, 40, true>,
                             cudaFuncAttributeMaxDynamicSharedMemorySize, SMEM);
        dim3 grid(BT / 64, 2);
        mma_gemm_kernel<200, 200, 204, 160, 40, true><<<grid, 256, SMEM>>>(
            nullptr, txt, emb, W_ih, b_ih, xp, 300);
    }

    fused_scan_kernel<<<Bz / 2, 480, 100 * 108 * 4>>>(
        W_hh, b_hh, W_ts, b_ts, W_ti, b_ti, W_lgr, b_lgr, lens);

    out_kernel<<<(Bz * NCz + 255) / 256, 256>>>(W_out, b_out, out);
}

// round 7
// speedup vs baseline: 1.4307x; 1.1355x over previous
#include <cuda_runtime.h>
#include <cstdint>

#define Bz   256
#define Tz   512
#define Ez   200
#define Hz   100
#define NCz  5
#define BT   131072      // B*T

typedef unsigned long long ull;

// ---------------- scratch ----------------
__device__ float g_scale[BT];
__device__ float g_xp[(size_t)BT * 300];   // 157 MB
__device__ float g_state[Bz * Hz];

// ---------------- helpers ----------------
__device__ __forceinline__ float sigf(float x) {
    return 1.0f / (1.0f + __expf(-x));
}
__device__ __forceinline__ float tanh_fast(float x) {
    float t = __expf(-2.0f * fabsf(x));
    float r = (1.0f - t) / (1.0f + t);
    return copysignf(r, x);
}
__device__ __forceinline__ float to_tf32(float x) {
    uint32_t u;
    asm("cvt.rna.tf32.f32 %0, %1;" : "=r"(u) : "f"(x));
    return __uint_as_float(u);
}
__device__ __forceinline__ void fma2(ull& d, ull a, ull b) {
    asm("fma.rn.f32x2 %0, %1, %2, %0;" : "+l"(d) : "l"(a), "l"(b));
}
__device__ __forceinline__ float upksum(ull v) {
    float lo, hi;
    asm("mov.b64 {%0,%1}, %2;" : "=f"(lo), "=f"(hi) : "l"(v));
    return lo + hi;
}

// ---------------- K1: per-row embedding norm scale ----------------
__global__ void __launch_bounds__(256) scale_kernel(const int* __restrict__ txt,
                                                    const float* __restrict__ emb) {
    int warp = (blockIdx.x * 256 + threadIdx.x) >> 5;
    int lane = threadIdx.x & 31;
    if (warp >= BT) return;
    int tok = txt[warp];
    const float* row = emb + (size_t)tok * Ez;
    float ss = 0.f;
    for (int k = lane; k < Ez; k += 32) { float v = row[k]; ss += v * v; }
    #pragma unroll
    for (int o = 16; o > 0; o >>= 1) ss += __shfl_xor_sync(0xffffffffu, ss, o);
    if (lane == 0) {
        float n = sqrtf(ss);
        g_scale[warp] = (n > 1.0f) ? 1.0f / (n + 1e-7f) : 1.0f;
    }
}

// ---------------- K2: tf32 MMA GEMM (xp = norm(emb[txt]) @ W_ih^T + b_ih) ----------------
template <int KDIM, int KCEIL, int KSTR, int TN, int WNc, bool GATHER>
__global__ void __launch_bounds__(256) mma_gemm_kernel(
    const float* __restrict__ Ain,
    const int* __restrict__ txt,
    const float* __restrict__ emb,
    const float* __restrict__ W,
    const float* __restrict__ bias,
    float* __restrict__ C,
    int NV)
{
    extern __shared__ float sm[];
    float* As = sm;
    float* Bs = sm + 64 * KSTR;
    __shared__ int   s_tok[64];
    __shared__ float s_scl[64];

    const int tid   = threadIdx.x;
    const int rbase = blockIdx.x * 64;
    const int nbase = blockIdx.y * TN;

    if (GATHER) {
        if (tid < 64) {
            int r = rbase + tid;
            s_tok[tid] = txt[r];
            s_scl[tid] = g_scale[r];
        }
        __syncthreads();
    }

    const int K4 = KCEIL / 4;
    for (int e = tid; e < 64 * K4; e += 256) {
        int row = e / K4, k4 = e % K4;
        float4 v = make_float4(0.f, 0.f, 0.f, 0.f);
        if (4 * k4 + 3 < KDIM) {
            if (GATHER) {
                const float4* p = (const float4*)(emb + (size_t)s_tok[row] * KDIM) + k4;
                v = *p;
                float s = s_scl[row];
                v.x *= s; v.y *= s; v.z *= s; v.w *= s;
            } else {
                const float4* p = (const float4*)(Ain + (size_t)(rbase + row) * KDIM) + k4;
                v = *p;
            }
        }
        float4 o = make_float4(to_tf32(v.x), to_tf32(v.y), to_tf32(v.z), to_tf32(v.w));
        *(float4*)(As + row * KSTR + 4 * k4) = o;
    }
    for (int e = tid; e < TN * K4; e += 256) {
        int n = e / K4, k4 = e % K4;
        int ng = nbase + n;
        float4 v = make_float4(0.f, 0.f, 0.f, 0.f);
        if (ng < NV && 4 * k4 + 3 < KDIM) {
            const float4* p = (const float4*)(W + (size_t)ng * KDIM) + k4;
            v = *p;
        }
        float4 o = make_float4(to_tf32(v.x), to_tf32(v.y), to_tf32(v.z), to_tf32(v.w));
        *(float4*)(Bs + n * KSTR + 4 * k4) = o;
    }
    __syncthreads();

    const int wid  = tid >> 5;
    const int lane = tid & 31;
    const int g    = lane >> 2;
    const int tg   = lane & 3;
    const int mwarp = wid & 1;
    const int nwarp = wid >> 1;
    const int NF = WNc / 8;

    float c[2][NF][4];
    #pragma unroll
    for (int mt = 0; mt < 2; mt++)
        #pragma unroll
        for (int nf = 0; nf < NF; nf++)
            #pragma unroll
            for (int i = 0; i < 4; i++) c[mt][nf][i] = 0.f;

    const float* Aw = As + (mwarp * 32) * KSTR;
    const float* Bw = Bs + (nwarp * WNc) * KSTR;

    #pragma unroll 1
    for (int k8 = 0; k8 < KCEIL / 8; k8++) {
        int k0 = k8 * 8;
        uint32_t a[2][4], b[NF][2];
        #pragma unroll
        for (int mt = 0; mt < 2; mt++) {
            const float* ap = Aw + (mt * 16 + g) * KSTR + k0 + tg;
            a[mt][0] = __float_as_uint(ap[0]);
            a[mt][1] = __float_as_uint(ap[8 * KSTR]);
            a[mt][2] = __float_as_uint(ap[4]);
            a[mt][3] = __float_as_uint(ap[8 * KSTR + 4]);
        }
        #pragma unroll
        for (int nf = 0; nf < NF; nf++) {
            const float* bp = Bw + (nf * 8 + g) * KSTR + k0 + tg;
            b[nf][0] = __float_as_uint(bp[0]);
            b[nf][1] = __float_as_uint(bp[4]);
        }
        #pragma unroll
        for (int mt = 0; mt < 2; mt++)
            #pragma unroll
            for (int nf = 0; nf < NF; nf++) {
                asm volatile(
                    "mma.sync.aligned.m16n8k8.row.col.f32.tf32.tf32.f32 "
                    "{%0,%1,%2,%3}, {%4,%5,%6,%7}, {%8,%9}, {%0,%1,%2,%3};"
                    : "+f"(c[mt][nf][0]), "+f"(c[mt][nf][1]),
                      "+f"(c[mt][nf][2]), "+f"(c[mt][nf][3])
                    : "r"(a[mt][0]), "r"(a[mt][1]), "r"(a[mt][2]), "r"(a[mt][3]),
                      "r"(b[nf][0]), "r"(b[nf][1]));
            }
    }

    #pragma unroll
    for (int mt = 0; mt < 2; mt++) {
        int row = rbase + mwarp * 32 + mt * 16 + g;
        #pragma unroll
        for (int nf = 0; nf < NF; nf++) {
            int col = nbase + nwarp * WNc + nf * 8 + 2 * tg;
            if (col < NV) {
                float b0 = bias[col], b1 = bias[col + 1];
                float2 v0 = make_float2(c[mt][nf][0] + b0, c[mt][nf][1] + b1);
                float2 v1 = make_float2(c[mt][nf][2] + b0, c[mt][nf][3] + b1);
                *(float2*)(C + (size_t)row * NV + col) = v0;
                *(float2*)(C + (size_t)(row + 8) * NV + col) = v1;
            }
        }
    }
}

// ============================================================================
// Fused scan, uniform-GEMV design. 128 blocks (2 batches), 512 threads:
//   tid 0-499 : ONE uniform GEMV role, row r = tid.
//       r <300 : W_hh row, source hb, out -> outp[b][r]       (GRU pre-act)
//       r <400 : W_ti row, source hb, out -> outp[b][r]       (ti)
//       r <500 : W_ts row, source stb, out -> outp[b][r]      (m)
//     Weights in w[50] ull regs; all smem GEMV loads are warp-broadcast
//     LDS.128 (conflict-free). No role branches inside the loop.
//   tid 500-511 (lanes 20-31 of warp 15): z/li/pg reductions via shared partials.
//   phase 2: tid<100 h-update; tid 400-499 st-update + x prefetch.
// Loop s = 0..Tz. 2 barriers/superstep. Boundary steps compute harmless
// garbage from zeroed buffers instead of branching.
// ============================================================================
__global__ void __launch_bounds__(512, 1) fused_scan_kernel(
    const float* __restrict__ Whh, const float* __restrict__ bhh,
    const float* __restrict__ Wts, const float* __restrict__ bts,
    const float* __restrict__ Wti, const float* __restrict__ bti,
    const float* __restrict__ Wlgr, const float* __restrict__ blgr,
    const int* __restrict__ lens)
{
    __shared__ __align__(16) float hb[2][2][104];    // h double buffer
    __shared__ __align__(16) float stb[2][2][104];   // st double buffer
    __shared__ float outp[2][512];                   // GEMV outputs [batch][row]
    __shared__ float xbuf[2][2][304];                // x double buffer
    __shared__ float wlgr_s[100], wl_s[100];
    __shared__ float redpart[12][8];
    __shared__ float redv[4];                        // z0,z1,g0,g1
    __shared__ float sblg;
    __shared__ int   slen[2];

    const int tid = threadIdx.x;
    const int b0 = blockIdx.x * 2;
    const float* xp0 = g_xp + (size_t)b0 * Tz * 300;
    const float* xp1 = xp0 + (size_t)Tz * 300;

    const bool isG   = (tid < 500);
    const bool isC   = (tid >= 400 && tid < 500);

    // ---- init shared ----
    if (tid < 104) {
        hb[0][0][tid] = 0.f;  hb[0][1][tid] = 0.f;
        hb[1][0][tid] = 0.f;  hb[1][1][tid] = 0.f;
        stb[0][0][tid] = 0.f; stb[0][1][tid] = 0.f;
        stb[1][0][tid] = 0.f; stb[1][1][tid] = 0.f;
    }
    if (tid >= 104 && tid < 204) {
        int k = tid - 104;
        wlgr_s[k] = Wlgr[k];
        wl_s[k]   = Wlgr[100 + k];
    }
    if (tid == 500) { slen[0] = lens[b0]; slen[1] = lens[b0 + 1]; sblg = blgr[0]; }

    // ---- uniform GEMV setup ----
    ull w[50];
    float bias_r = 0.f, bts_r = 0.f;
    const float* srcP0 = nullptr;    // parity-0 source base (batch 0)
    float* tgt = nullptr;
    if (isG) {
        const float* wsrc;
        if (tid < 300)      { wsrc = Whh + tid * 100;         bias_r = bhh[tid]; }
        else if (tid < 400) { wsrc = Wti + (tid - 300) * 100; bias_r = bti[tid - 300]; }
        else                { wsrc = Wts + (tid - 400) * 100; bts_r = bts[tid - 400]; }
        const ull* wp = (const ull*)wsrc;
        #pragma unroll
        for (int q = 0; q < 50; q++) w[q] = wp[q];
        srcP0 = (tid < 400) ? &hb[0][0][0] : &stb[0][0][0];
        tgt = &outp[0][tid];
    }
    if (isC) {               // prologue: x_0 -> xbuf[0]
        int j = tid - 400;
        xbuf[0][0][j]       = xp0[j];        xbuf[0][1][j]       = xp1[j];
        xbuf[0][0][100 + j] = xp0[100 + j];  xbuf[0][1][100 + j] = xp1[100 + j];
        xbuf[0][0][200 + j] = xp0[200 + j];  xbuf[0][1][200 + j] = xp1[200 + j];
    }
    __syncthreads();

    for (int s = 0; s <= Tz; s++) {
        const int pp = (s & 1) ^ 1;          // parity holding h_{s-1} / st_{s-2}
        const int pc = s & 1;

        // ================= phase 1 =================
        if (isG) {
            // batch 0
            const ulonglong2* H = (const ulonglong2*)(srcP0 + (pp ? 208 : 0));
            ull aA = 0ull, aB = 0ull;
            #pragma unroll
            for (int v = 0; v < 25; v++) {
                ulonglong2 h = H[v];
                fma2(aA, w[2 * v],     h.x);
                fma2(aB, w[2 * v + 1], h.y);
            }
            float o0 = bias_r + upksum(aA) + upksum(aB);
            // batch 1: +104 floats = 416 bytes = +26 ulonglong2
            const ulonglong2* H2 = H + 26;
            ull cA = 0ull, cB = 0ull;
            #pragma unroll
            for (int v = 0; v < 25; v++) {
                ulonglong2 h = H2[v];
                fma2(cA, w[2 * v],     h.x);
                fma2(cB, w[2 * v + 1], h.y);
            }
            float o1 = bias_r + upksum(cA) + upksum(cB);
            tgt[0]   = o0;
            tgt[512] = o1;
        } else if (s >= 1) {
            // red lanes 500-511 (lanes 20-31 of warp 15)
            int k0 = tid - 500;
            float p0 = 0.f, p1 = 0.f, p2 = 0.f, p3 = 0.f;
            float p4 = 0.f, p5 = 0.f, p6 = 0.f, p7 = 0.f;
            for (int k = k0; k < 100; k += 12) {
                float h0 = hb[pp][0][k], h1 = hb[pp][1][k];
                float wg = wlgr_s[k], wl = wl_s[k];
                p0 += h0; p1 += h0 * h0; p2 += h0 * wg;
                p3 += h1; p4 += h1 * h1; p5 += h1 * wg;
                p6 += wl * stb[pp][0][k];
                p7 += wl * stb[pp][1][k];
            }
            redpart[k0][0] = p0; redpart[k0][1] = p1; redpart[k0][2] = p2;
            redpart[k0][3] = p3; redpart[k0][4] = p4; redpart[k0][5] = p5;
            redpart[k0][6] = p6; redpart[k0][7] = p7;
            __syncwarp(0xFFF00000u);
            if (k0 == 0) {
                float t0 = 0.f, t1 = 0.f, t2 = 0.f, t3 = 0.f;
                float t4 = 0.f, t5 = 0.f, t6 = 0.f, t7 = 0.f;
                #pragma unroll
                for (int i = 0; i < 12; i++) {
                    t0 += redpart[i][0]; t1 += redpart[i][1]; t2 += redpart[i][2];
                    t3 += redpart[i][3]; t4 += redpart[i][4]; t5 += redpart[i][5];
                    t6 += redpart[i][6]; t7 += redpart[i][7];
                }
                int t = s - 1;
                float att0 = 0.001f * t0 / fmaxf(sqrtf(t1), 1e-12f);
                float att1 = 0.001f * t3 / fmaxf(sqrtf(t4), 1e-12f);
                redv[0] = (t < slen[0] && att0 > 0.f) ? att0 : 0.f;
                redv[1] = (t < slen[1] && att1 > 0.f) ? att1 : 0.f;
                redv[2] = sigf(t2 + t6 + sblg);
                redv[3] = sigf(t5 + t7 + sblg);
            }
        }
        __syncthreads();

        // ================= phase 2 =================
        if (tid < 100) {
            if (s < Tz) {
                // GRU h-update for row tid
                float hr0 = outp[0][tid], hz0 = outp[0][100 + tid], hn0 = outp[0][200 + tid];
                float hr1 = outp[1][tid], hz1 = outp[1][100 + tid], hn1 = outp[1][200 + tid];
                float xr0 = xbuf[pc][0][tid],       xr1 = xbuf[pc][1][tid];
                float xz0 = xbuf[pc][0][100 + tid], xz1 = xbuf[pc][1][100 + tid];
                float xn0 = xbuf[pc][0][200 + tid], xn1 = xbuf[pc][1][200 + tid];
                float ho0 = hb[pp][0][tid], ho1 = hb[pp][1][tid];
                float r0 = sigf(xr0 + hr0), r1 = sigf(xr1 + hr1);
                float z0 = sigf(xz0 + hz0), z1 = sigf(xz1 + hz1);
                float n0 = tanh_fast(xn0 + r0 * hn0);
                float n1 = tanh_fast(xn1 + r1 * hn1);
                hb[pc][0][tid] = (1.f - z0) * n0 + z0 * ho0;
                hb[pc][1][tid] = (1.f - z1) * n1 + z1 * ho1;
            }
        } else if (isC) {
            int j = tid - 400;
            if (s <= Tz - 2) {
                // prefetch x_{s+1}
                const float* q0 = xp0 + (size_t)(s + 1) * 300;
                const float* q1 = xp1 + (size_t)(s + 1) * 300;
                int px = (s + 1) & 1;
                xbuf[px][0][j]       = q0[j];        xbuf[px][1][j]       = q1[j];
                xbuf[px][0][100 + j] = q0[100 + j];  xbuf[px][1][100 + j] = q1[100 + j];
                xbuf[px][0][200 + j] = q0[200 + j];  xbuf[px][1][200 + j] = q1[200 + j];
            }
            if (s >= 1) {
                // rec state update for t = s-1
                float ti0 = outp[0][300 + j], ti1 = outp[1][300 + j];
                float m0  = outp[0][400 + j], m1  = outp[1][400 + j];
                float z0 = redv[0], z1 = redv[1];
                float g0 = redv[2], g1 = redv[3];
                float so0 = stb[pp][0][j], so1 = stb[pp][1][j];
                float ns0 = tanh_fast(ti0 + g0 * m0 + bts_r);
                float ns1 = tanh_fast(ti1 + g1 * m1 + bts_r);
                stb[pc][0][j] = (1.f - z0) * so0 + z0 * ns0;
                stb[pc][1][j] = (1.f - z1) * so1 + z1 * ns1;
            }
        }
        __syncthreads();
    }

    // last st write was at s=Tz into parity 0
    if (isC) {
        int j = tid - 400;
        g_state[b0 * Hz + j]       = stb[0][0][j];
        g_state[(b0 + 1) * Hz + j] = stb[0][1][j];
    }
}

// ---------------- K7: output projection ----------------
__global__ void __launch_bounds__(256) out_kernel(const float* __restrict__ Wout,
                                                  const float* __restrict__ bout,
                                                  float* __restrict__ out) {
    int idx = blockIdx.x * 256 + threadIdx.x;
    if (idx >= Bz * NCz) return;
    int b = idx / NCz, c = idx % NCz;
    float acc = bout[c];
    const float* s = g_state + b * Hz;
    const float* wr = Wout + c * Hz;
    #pragma unroll
    for (int k = 0; k < Hz; k++) acc += s[k] * wr[k];
    out[idx] = acc;
}

// ---------------- launch ----------------
extern "C" void kernel_launch(void* const* d_in, const int* in_sizes, int n_in,
                              void* d_out, int out_size) {
    const int*   txt   = (const int*)d_in[0];
    const int*   lens  = (const int*)d_in[1];
    const float* emb   = (const float*)d_in[2];
    const float* W_ih  = (const float*)d_in[3];
    const float* W_hh  = (const float*)d_in[4];
    const float* b_ih  = (const float*)d_in[5];
    const float* b_hh  = (const float*)d_in[6];
    const float* W_lgr = (const float*)d_in[7];
    const float* b_lgr = (const float*)d_in[8];
    const float* W_ts  = (const float*)d_in[9];
    const float* b_ts  = (const float*)d_in[10];
    const float* W_ti  = (const float*)d_in[11];
    const float* b_ti  = (const float*)d_in[12];
    const float* W_out = (const float*)d_in[13];
    const float* b_out = (const float*)d_in[14];
    float* out = (float*)d_out;

    float* xp = nullptr; cudaGetSymbolAddress((void**)&xp, g_xp);

    scale_kernel<<<BT / 8, 256>>>(txt, emb);

    {
        constexpr int SMEM = (64 + 160) * 204 * 4;
        cudaFuncSetAttribute((const void*)mma_gemm_kernel<200, 200, 204, 160, 40, true>,
                             cudaFuncAttributeMaxDynamicSharedMemorySize, SMEM);
        dim3 grid(BT / 64, 2);
        mma_gemm_kernel<200, 200, 204, 160, 40, true><<<grid, 256, SMEM>>>(
            nullptr, txt, emb, W_ih, b_ih, xp, 300);
    }

    fused_scan_kernel<<<Bz / 2, 512>>>(W_hh, b_hh, W_ts, b_ts, W_ti, b_ti,
                                       W_lgr, b_lgr, lens);

    out_kernel<<<(Bz * NCz + 255) / 256, 256>>>(W_out, b_out, out);
}